// round 5
// baseline (speedup 1.0000x reference)
#include <cuda_runtime.h>

// LIF recurrence: B=64, T=1000, H=512, fp32.
// One thread per (b, h) neuron; sequential scan over T.
// Fine-grained software pipeline: at compute step u of chunk c we issue the
// load for element u of chunk c+1 (double-buffered, U=50). Load issue is
// continuous (1 per step) so the DRAM queue never drains; per-step asm
// scheduling barriers stop ptxas from re-front-batching the loads.

#define LIF_B 64
#define LIF_T 1000
#define LIF_H 512
#define LIF_U 50          // chunk size; 1000 = 20 * 50
#define LIF_BLOCK 64

#define LIF_STEP(BUF_IN, u)                                            \
    do {                                                               \
        float memr = spiked ? 0.0f : mem;                              \
        mem = fmaf(alpha, memr, a1 * syn);                             \
        syn = fmaf(b1, (BUF_IN)[u], beta * syn);                       \
        spiked = (mem >= th);                                          \
        __stcs(op + (u) * LIF_H, spiked ? 1.0f : 0.0f);                \
    } while (0)

__global__ __launch_bounds__(LIF_BLOCK, 4) void LIF_30554397344397_kernel(
    const float* __restrict__ x,       // (B, T, H)
    const float* __restrict__ dc,      // (2,)  [alpha, beta] before clamping
    const float* __restrict__ thp,     // ()    threshold
    float* __restrict__ out)           // (B, T, H) spikes
{
    const int idx = blockIdx.x * LIF_BLOCK + threadIdx.x;   // 0 .. B*H-1
    const int b = idx >> 9;        // / 512
    const int h = idx & (LIF_H - 1);

    const float alpha = fminf(fmaxf(dc[0], 0.5f), 1.0f);
    const float beta  = fminf(fmaxf(dc[1], 0.5f), 1.0f);
    const float th    = thp[0];
    const float a1 = 1.0f - alpha;
    const float b1 = 1.0f - beta;

    const float* xp = x   + (size_t)b * (LIF_T * LIF_H) + h;
    float*       op = out + (size_t)b * (LIF_T * LIF_H) + h;

    float mem = 0.0f, syn = 0.0f;
    bool  spiked = false;

    float va[LIF_U], vb[LIF_U];   // static double buffers (stay in regs)

    // Prologue: prefetch chunk 0 into va (the only front-batch).
    #pragma unroll
    for (int u = 0; u < LIF_U; u++) va[u] = __ldcs(xp + u * LIF_H);

    // Main loop: chunks 0..17, two per iteration (static buffer roles).
    // Each compute step also issues exactly one load for the next chunk.
    for (int c = 0; c < 18; c += 2) {
        const float* xp1 = xp + LIF_U * LIF_H;      // chunk c+1
        const float* xp2 = xp + 2 * LIF_U * LIF_H;  // chunk c+2

        // Compute chunk c from va; prefetch chunk c+1 into vb, one per step.
        #pragma unroll
        for (int u = 0; u < LIF_U; u++) {
            vb[u] = __ldcs(xp1 + u * LIF_H);
            LIF_STEP(va, u);
            asm volatile("" ::: "memory");   // pin load/store into this step
        }
        op += LIF_U * LIF_H;

        // Compute chunk c+1 from vb; prefetch chunk c+2 into va.
        #pragma unroll
        for (int u = 0; u < LIF_U; u++) {
            va[u] = __ldcs(xp2 + u * LIF_H);
            LIF_STEP(vb, u);
            asm volatile("" ::: "memory");
        }
        op += LIF_U * LIF_H;
        xp = xp2;
    }

    // Epilogue: chunk 18 from va (prefetch 19 into vb), then 19 (no prefetch).
    {
        const float* xp1 = xp + LIF_U * LIF_H;
        #pragma unroll
        for (int u = 0; u < LIF_U; u++) {
            vb[u] = __ldcs(xp1 + u * LIF_H);
            LIF_STEP(va, u);
            asm volatile("" ::: "memory");
        }
        op += LIF_U * LIF_H;

        #pragma unroll
        for (int u = 0; u < LIF_U; u++) {
            LIF_STEP(vb, u);
        }
    }
}

extern "C" void kernel_launch(void* const* d_in, const int* in_sizes, int n_in,
                              void* d_out, int out_size) {
    const float* x   = (const float*)d_in[0];  // (B, T, H) float32
    const float* dc  = (const float*)d_in[1];  // (2,) float32
    const float* thp = (const float*)d_in[2];  // scalar float32
    float* out = (float*)d_out;                // (B, T, H) float32

    const int total_threads = LIF_B * LIF_H;    // 32768
    const int grid = total_threads / LIF_BLOCK; // 512

    LIF_30554397344397_kernel<<<grid, LIF_BLOCK>>>(x, dc, thp, out);
}